// round 4
// baseline (speedup 1.0000x reference)
#include <cuda_runtime.h>

#define IN_CH  128
#define K_HOPS 3
#define MAX_N  10240

// Scratch: agg[n][k][c]  (15.7 MB, fits in L2)
__device__ float g_agg[(size_t)MAX_N * K_HOPS * IN_CH];
__device__ int   g_is64;   // 1 if edge_index is int64, 0 if int32

// ---------------------------------------------------------------------------
// Kernel 0: detect edge_index dtype. JAX without x64 silently produces int32
// even though the reference asks for int64. Interpreting packed int32 pairs
// as int64 yields values >= 2^32 almost surely, so a 64-sample range check
// discriminates perfectly.
// ---------------------------------------------------------------------------
__global__ void detect_idx_kernel(const void* ei, int E, int N) {
    if (threadIdx.x == 0 && blockIdx.x == 0) {
        const long long* p64 = (const long long*)ei;
        int ok = 1;
        int cnt = (E < 64) ? E : 64;
        for (int i = 0; i < cnt; i++) {
            long long v = p64[i];
            if (v < 0 || v >= (long long)N) { ok = 0; break; }
        }
        g_is64 = ok;
    }
}

// ---------------------------------------------------------------------------
// Kernel 1: zero the aggregation scratch
// ---------------------------------------------------------------------------
__global__ void zero_agg_kernel(int total4) {
    int i = blockIdx.x * blockDim.x + threadIdx.x;
    if (i < total4) {
        float4 z = make_float4(0.f, 0.f, 0.f, 0.f);
        reinterpret_cast<float4*>(g_agg)[i] = z;
    }
}

// ---------------------------------------------------------------------------
// Kernel 2: edge scatter.  One warp per edge.
//   agg[src, k, :] += X[e, k] * h[dst, :]
// Vector reduction (sm_90+): no return trip, 1 message per 16 bytes.
// ---------------------------------------------------------------------------
__device__ __forceinline__ void red_add_v4(float* p, float a, float b, float c, float d) {
    asm volatile("red.global.add.v4.f32 [%0], {%1, %2, %3, %4};"
                 :: "l"(p), "f"(a), "f"(b), "f"(c), "f"(d) : "memory");
}

__global__ __launch_bounds__(256) void scatter_edges_kernel(
    const float* __restrict__ h,
    const float* __restrict__ X,
    const void*  __restrict__ ei_raw,   // [2][E], int32 or int64
    int E, int N)
{
    int gw   = (blockIdx.x * blockDim.x + threadIdx.x) >> 5;  // edge id
    int lane = threadIdx.x & 31;
    if (gw >= E) return;

    int src, dst;
    if (g_is64) {
        const long long* ei = (const long long*)ei_raw;
        src = (int)__ldg(ei + gw);
        dst = (int)__ldg(ei + (size_t)E + gw);
    } else {
        const int* ei = (const int*)ei_raw;
        src = __ldg(ei + gw);
        dst = __ldg(ei + (size_t)E + gw);
    }
    if ((unsigned)src >= (unsigned)N || (unsigned)dst >= (unsigned)N) return;

    float x0 = __ldg(X + (size_t)gw * 3 + 0);
    float x1 = __ldg(X + (size_t)gw * 3 + 1);
    float x2 = __ldg(X + (size_t)gw * 3 + 2);

    // 32 lanes x float4 = 128 channels
    float4 hv = __ldg(reinterpret_cast<const float4*>(h + (size_t)dst * IN_CH) + lane);

    float* base = g_agg + (size_t)src * (K_HOPS * IN_CH) + lane * 4;
    red_add_v4(base,             hv.x * x0, hv.y * x0, hv.z * x0, hv.w * x0);
    red_add_v4(base + IN_CH,     hv.x * x1, hv.y * x1, hv.z * x1, hv.w * x1);
    red_add_v4(base + 2 * IN_CH, hv.x * x2, hv.y * x2, hv.z * x2, hv.w * x2);
}

// ---------------------------------------------------------------------------
// Kernel 3: fused per-hop GEMM + max over hops + bias.
//   out[n, o] = max_k( sum_i agg[n,k,i] * W[k,i,o] ) + bias[o]
// Tile: 64 nodes x 128 outputs per block, 256 threads,
//       each thread: 8 nodes x 4 outputs.
// ---------------------------------------------------------------------------
#define TM  64
#define IC  32
#define PAD (TM + 4)

__global__ __launch_bounds__(256) void gemm_max_bias_kernel(
    const float* __restrict__ W,     // [3][128][128]
    const float* __restrict__ bias,  // [128]
    float* __restrict__ out,         // [N][128]
    int N)
{
    __shared__ float sW[IC * IN_CH];   // 16 KB
    __shared__ float sA[IC * PAD];     // 8.7 KB

    const int tid = threadIdx.x;
    const int to  = tid & 31;   // output group: o = to*4 .. to*4+3
    const int tn  = tid >> 5;   // node group:   n = n0 + tn*8 .. +7
    const int n0  = blockIdx.x * TM;

    float M[8][4];
    #pragma unroll
    for (int j = 0; j < 8; j++)
        #pragma unroll
        for (int q = 0; q < 4; q++) M[j][q] = -3.0e38f;

    for (int k = 0; k < K_HOPS; k++) {
        float C[8][4];
        #pragma unroll
        for (int j = 0; j < 8; j++)
            #pragma unroll
            for (int q = 0; q < 4; q++) C[j][q] = 0.f;

        for (int ic = 0; ic < IN_CH; ic += IC) {
            __syncthreads();
            {
                const float4* Wg = reinterpret_cast<const float4*>(
                    W + ((size_t)k * IN_CH + ic) * IN_CH);
                float4* sW4 = reinterpret_cast<float4*>(sW);
                #pragma unroll
                for (int r = 0; r < 4; r++)
                    sW4[tid + r * 256] = __ldg(Wg + tid + r * 256);
            }
            #pragma unroll
            for (int r = 0; r < 8; r++) {
                int idx  = tid + r * 256;   // 0..2047
                int nn   = idx >> 5;        // 0..63
                int ii   = idx & 31;        // 0..31
                int node = n0 + nn;
                float v = 0.f;
                if (node < N)
                    v = g_agg[(size_t)node * (K_HOPS * IN_CH) + k * IN_CH + ic + ii];
                sA[ii * PAD + nn] = v;
            }
            __syncthreads();

            #pragma unroll 8
            for (int i = 0; i < IC; i++) {
                float4 b  = *reinterpret_cast<const float4*>(&sW[i * IN_CH + to * 4]);
                float4 a0 = *reinterpret_cast<const float4*>(&sA[i * PAD + tn * 8]);
                float4 a1 = *reinterpret_cast<const float4*>(&sA[i * PAD + tn * 8 + 4]);
                float av[8] = {a0.x, a0.y, a0.z, a0.w, a1.x, a1.y, a1.z, a1.w};
                #pragma unroll
                for (int j = 0; j < 8; j++) {
                    C[j][0] += av[j] * b.x;
                    C[j][1] += av[j] * b.y;
                    C[j][2] += av[j] * b.z;
                    C[j][3] += av[j] * b.w;
                }
            }
        }
        #pragma unroll
        for (int j = 0; j < 8; j++)
            #pragma unroll
            for (int q = 0; q < 4; q++)
                M[j][q] = fmaxf(M[j][q], C[j][q]);
    }

    float4 bv = __ldg(reinterpret_cast<const float4*>(bias) + to);
    #pragma unroll
    for (int j = 0; j < 8; j++) {
        int node = n0 + tn * 8 + j;
        if (node < N) {
            float4 o;
            o.x = M[j][0] + bv.x;
            o.y = M[j][1] + bv.y;
            o.z = M[j][2] + bv.z;
            o.w = M[j][3] + bv.w;
            reinterpret_cast<float4*>(out + (size_t)node * IN_CH)[to] = o;
        }
    }
}

// ---------------------------------------------------------------------------
// Launch.  Inputs (metadata order): h[f32 N*128], X[f32 E*3],
// edge_index[2*E, int32 OR int64], batch_node[f32 N] (unused),
// weight[f32 3*128*128], bias[f32 128].  Output: f32 [N][128].
// ---------------------------------------------------------------------------
extern "C" void kernel_launch(void* const* d_in, const int* in_sizes, int n_in,
                              void* d_out, int out_size) {
    const float* h    = (const float*)d_in[0];
    const float* X    = (const float*)d_in[1];
    const void*  ei   = d_in[2];
    const float* W    = (const float*)d_in[4];
    const float* bias = (const float*)d_in[5];
    float*       out  = (float*)d_out;

    int N = in_sizes[0] / IN_CH;
    int E = in_sizes[1] / K_HOPS;

    detect_idx_kernel<<<1, 32>>>(ei, E, N);

    int total4 = N * K_HOPS * IN_CH / 4;
    zero_agg_kernel<<<(total4 + 255) / 256, 256>>>(total4);

    int nblk = (E + 7) / 8;   // one warp per edge
    scatter_edges_kernel<<<nblk, 256>>>(h, X, ei, E, N);

    gemm_max_bias_kernel<<<(N + TM - 1) / TM, 256>>>(W, bias, out, N);
}

// round 5
// speedup vs baseline: 1.4061x; 1.4061x over previous
#include <cuda_runtime.h>

#define IN_CH  128
#define K_HOPS 3
#define MAX_N  10240
#define MAX_E  330000

// Scratch (all __device__ globals: allocation-guard-safe)
__device__ float  g_agg[(size_t)MAX_N * K_HOPS * IN_CH];   // [n][k][c] 15.7 MB
__device__ float4 g_packed[MAX_E];                          // {x0,x1,x2, bits(dst)} sorted by src
__device__ int    g_cnt[MAX_N + 1];
__device__ int    g_off[MAX_N + 1];
__device__ int    g_cur[MAX_N];
__device__ int    g_is64;

// ---------------------------------------------------------------------------
// Kernel 1: zero counts + detect edge_index dtype (JAX may emit int32).
// ---------------------------------------------------------------------------
__global__ void init_kernel(const void* ei, int E, int N) {
    int i = blockIdx.x * blockDim.x + threadIdx.x;
    if (i <= N) g_cnt[i] = 0;
    if (i == 0) {
        const long long* p64 = (const long long*)ei;
        int ok = 1;
        int cnt = (E < 64) ? E : 64;
        for (int j = 0; j < cnt; j++) {
            long long v = p64[j];
            if (v < 0 || v >= (long long)N) { ok = 0; break; }
        }
        g_is64 = ok;
    }
}

// ---------------------------------------------------------------------------
// Kernel 2: histogram of src
// ---------------------------------------------------------------------------
__global__ void count_kernel(const void* __restrict__ ei, int E, int N) {
    int e = blockIdx.x * blockDim.x + threadIdx.x;
    if (e >= E) return;
    int src = g_is64 ? (int)((const long long*)ei)[e] : ((const int*)ei)[e];
    if ((unsigned)src < (unsigned)N) atomicAdd(&g_cnt[src], 1);
}

// ---------------------------------------------------------------------------
// Kernel 3: exclusive scan (single block, 1024 threads) -> offsets + cursors
// ---------------------------------------------------------------------------
__global__ __launch_bounds__(1024) void scan_kernel(int N) {
    __shared__ int part[1024];
    int t = threadIdx.x;
    int chunk = (N + 1023) / 1024;
    int b0 = t * chunk;
    int b1 = b0 + chunk; if (b1 > N) b1 = N;
    int s = 0;
    for (int i = b0; i < b1; i++) s += g_cnt[i];
    part[t] = s;
    __syncthreads();
    for (int off = 1; off < 1024; off <<= 1) {
        int add = (t >= off) ? part[t - off] : 0;
        __syncthreads();
        part[t] += add;
        __syncthreads();
    }
    int run = part[t] - s;     // exclusive prefix of this thread's chunk
    for (int i = b0; i < b1; i++) {
        g_off[i] = run;
        g_cur[i] = run;
        run += g_cnt[i];
    }
    if (t == 1023) g_off[N] = part[1023];
}

// ---------------------------------------------------------------------------
// Kernel 4: permute edges into src-sorted packed records
// ---------------------------------------------------------------------------
__global__ void permute_kernel(const void* __restrict__ ei,
                               const float* __restrict__ X,
                               int E, int N) {
    int e = blockIdx.x * blockDim.x + threadIdx.x;
    if (e >= E) return;
    int src, dst;
    if (g_is64) {
        const long long* p = (const long long*)ei;
        src = (int)p[e];
        dst = (int)p[(size_t)E + e];
    } else {
        const int* p = (const int*)ei;
        src = p[e];
        dst = p[(size_t)E + e];
    }
    if ((unsigned)src >= (unsigned)N || (unsigned)dst >= (unsigned)N) return;
    float x0 = __ldg(X + (size_t)e * 3 + 0);
    float x1 = __ldg(X + (size_t)e * 3 + 1);
    float x2 = __ldg(X + (size_t)e * 3 + 2);
    int pos = atomicAdd(&g_cur[src], 1);
    g_packed[pos] = make_float4(x0, x1, x2, __int_as_float(dst));
}

// ---------------------------------------------------------------------------
// Kernel 5: gather-aggregate.  One warp per node; lane owns 4 channels.
//   agg[n,k,:] = sum_{e in CSR[n]} X[e,k] * h[dst[e],:]
// Writes every node (zero-degree nodes write zeros) -> no zero pass needed.
// ---------------------------------------------------------------------------
__global__ __launch_bounds__(256) void gather_kernel(
    const float* __restrict__ h, int N) {
    int w    = (blockIdx.x * blockDim.x + threadIdx.x) >> 5;   // node
    int lane = threadIdx.x & 31;
    if (w >= N) return;

    int beg = __ldg(&g_off[w]);
    int end = __ldg(&g_off[w + 1]);

    float4 a0 = make_float4(0.f, 0.f, 0.f, 0.f);
    float4 a1 = a0, a2 = a0;

    int e = beg;
    for (; e + 1 < end; e += 2) {
        float4 p0 = __ldg(&g_packed[e]);
        float4 p1 = __ldg(&g_packed[e + 1]);
        int d0 = __float_as_int(p0.w);
        int d1 = __float_as_int(p1.w);
        float4 h0 = __ldg(reinterpret_cast<const float4*>(h + (size_t)d0 * IN_CH) + lane);
        float4 h1 = __ldg(reinterpret_cast<const float4*>(h + (size_t)d1 * IN_CH) + lane);
        a0.x += p0.x * h0.x; a0.y += p0.x * h0.y; a0.z += p0.x * h0.z; a0.w += p0.x * h0.w;
        a1.x += p0.y * h0.x; a1.y += p0.y * h0.y; a1.z += p0.y * h0.z; a1.w += p0.y * h0.w;
        a2.x += p0.z * h0.x; a2.y += p0.z * h0.y; a2.z += p0.z * h0.z; a2.w += p0.z * h0.w;
        a0.x += p1.x * h1.x; a0.y += p1.x * h1.y; a0.z += p1.x * h1.z; a0.w += p1.x * h1.w;
        a1.x += p1.y * h1.x; a1.y += p1.y * h1.y; a1.z += p1.y * h1.z; a1.w += p1.y * h1.w;
        a2.x += p1.z * h1.x; a2.y += p1.z * h1.y; a2.z += p1.z * h1.z; a2.w += p1.z * h1.w;
    }
    if (e < end) {
        float4 p0 = __ldg(&g_packed[e]);
        int d0 = __float_as_int(p0.w);
        float4 h0 = __ldg(reinterpret_cast<const float4*>(h + (size_t)d0 * IN_CH) + lane);
        a0.x += p0.x * h0.x; a0.y += p0.x * h0.y; a0.z += p0.x * h0.z; a0.w += p0.x * h0.w;
        a1.x += p0.y * h0.x; a1.y += p0.y * h0.y; a1.z += p0.y * h0.z; a1.w += p0.y * h0.w;
        a2.x += p0.z * h0.x; a2.y += p0.z * h0.y; a2.z += p0.z * h0.z; a2.w += p0.z * h0.w;
    }

    float4* base = reinterpret_cast<float4*>(g_agg + (size_t)w * (K_HOPS * IN_CH));
    base[lane]      = a0;
    base[32 + lane] = a1;
    base[64 + lane] = a2;
}

// ---------------------------------------------------------------------------
// Kernel 6: fused per-hop GEMM + max over hops + bias.
//   out[n,o] = max_k( sum_i agg[n,k,i] * W[k,i,o] ) + bias[o]
// CTA: 32 nodes x 128 outs, 256 threads, thread 4n x 4o.
// sA: transposed agg slice [i][node] (128x32, staged once per hop).
// sW: W chunk [64][128] (two chunks per hop).  48 KB static smem, 2 CTAs/SM.
// ---------------------------------------------------------------------------
#define TMG 32

__global__ __launch_bounds__(256, 2) void gemm_max_bias_kernel(
    const float* __restrict__ W,     // [3][128][128]
    const float* __restrict__ bias,  // [128]
    float* __restrict__ out,         // [N][128]
    int N)
{
    __shared__ float sW[64 * IN_CH];   // 32 KB
    __shared__ float sA[IN_CH * TMG];  // 16 KB

    const int tid = threadIdx.x;
    const int to  = tid & 31;    // o group: o = to*4
    const int tn  = tid >> 5;    // n group: n = n0 + tn*4 .. +3
    const int n0  = blockIdx.x * TMG;

    float M[4][4];
    #pragma unroll
    for (int j = 0; j < 4; j++)
        #pragma unroll
        for (int q = 0; q < 4; q++) M[j][q] = -3.0e38f;

    for (int k = 0; k < K_HOPS; k++) {
        float C[4][4];
        #pragma unroll
        for (int j = 0; j < 4; j++)
            #pragma unroll
            for (int q = 0; q < 4; q++) C[j][q] = 0.f;

        __syncthreads();   // protect sA/sW from previous iteration's readers

        // Stage sA: full 128-i slice for this hop, transposed [i][node].
        // idx -> nn = lane (conflict-free scalar STS), ig = float4 group of i.
        #pragma unroll
        for (int r = 0; r < 4; r++) {
            int idx = tid + r * 256;        // 0..1023
            int nn  = idx & 31;
            int ig  = idx >> 5;             // 0..31
            int node = n0 + nn;
            float4 v = make_float4(0.f, 0.f, 0.f, 0.f);
            if (node < N)
                v = __ldg(reinterpret_cast<const float4*>(
                        g_agg + (size_t)node * (K_HOPS * IN_CH) + k * IN_CH + ig * 4));
            sA[(ig * 4 + 0) * TMG + nn] = v.x;
            sA[(ig * 4 + 1) * TMG + nn] = v.y;
            sA[(ig * 4 + 2) * TMG + nn] = v.z;
            sA[(ig * 4 + 3) * TMG + nn] = v.w;
        }

        #pragma unroll
        for (int c = 0; c < 2; c++) {
            if (c > 0) __syncthreads();     // previous chunk compute done
            // Stage sW chunk: rows k*128+c*64 .. +63, coalesced float4
            {
                const float4* Wg = reinterpret_cast<const float4*>(
                    W + ((size_t)k * IN_CH + c * 64) * IN_CH);
                float4* sW4 = reinterpret_cast<float4*>(sW);
                #pragma unroll
                for (int r = 0; r < 8; r++)
                    sW4[tid + r * 256] = __ldg(Wg + tid + r * 256);
            }
            __syncthreads();

            #pragma unroll 8
            for (int i = 0; i < 64; i++) {
                float4 b = *reinterpret_cast<const float4*>(&sW[i * IN_CH + to * 4]);
                float4 a = *reinterpret_cast<const float4*>(&sA[(c * 64 + i) * TMG + tn * 4]);
                C[0][0] += a.x * b.x; C[0][1] += a.x * b.y; C[0][2] += a.x * b.z; C[0][3] += a.x * b.w;
                C[1][0] += a.y * b.x; C[1][1] += a.y * b.y; C[1][2] += a.y * b.z; C[1][3] += a.y * b.w;
                C[2][0] += a.z * b.x; C[2][1] += a.z * b.y; C[2][2] += a.z * b.z; C[2][3] += a.z * b.w;
                C[3][0] += a.w * b.x; C[3][1] += a.w * b.y; C[3][2] += a.w * b.z; C[3][3] += a.w * b.w;
            }
        }

        #pragma unroll
        for (int j = 0; j < 4; j++)
            #pragma unroll
            for (int q = 0; q < 4; q++)
                M[j][q] = fmaxf(M[j][q], C[j][q]);
    }

    float4 bv = __ldg(reinterpret_cast<const float4*>(bias) + to);
    #pragma unroll
    for (int j = 0; j < 4; j++) {
        int node = n0 + tn * 4 + j;
        if (node < N) {
            float4 o;
            o.x = M[j][0] + bv.x;
            o.y = M[j][1] + bv.y;
            o.z = M[j][2] + bv.z;
            o.w = M[j][3] + bv.w;
            reinterpret_cast<float4*>(out + (size_t)node * IN_CH)[to] = o;
        }
    }
}

// ---------------------------------------------------------------------------
// Launch.  Inputs (metadata order): h[f32 N*128], X[f32 E*3],
// edge_index[2*E, int32 OR int64], batch_node[f32 N] (unused),
// weight[f32 3*128*128], bias[f32 128].  Output: f32 [N][128].
// ---------------------------------------------------------------------------
extern "C" void kernel_launch(void* const* d_in, const int* in_sizes, int n_in,
                              void* d_out, int out_size) {
    const float* h    = (const float*)d_in[0];
    const float* X    = (const float*)d_in[1];
    const void*  ei   = d_in[2];
    const float* W    = (const float*)d_in[4];
    const float* bias = (const float*)d_in[5];
    float*       out  = (float*)d_out;

    int N = in_sizes[0] / IN_CH;
    int E = in_sizes[1] / K_HOPS;

    init_kernel<<<(N + 1 + 255) / 256, 256>>>(ei, E, N);
    count_kernel<<<(E + 255) / 256, 256>>>(ei, E, N);
    scan_kernel<<<1, 1024>>>(N);
    permute_kernel<<<(E + 255) / 256, 256>>>(ei, X, E, N);
    gather_kernel<<<(N + 7) / 8, 256>>>(h, N);   // one warp per node
    gemm_max_bias_kernel<<<(N + TMG - 1) / TMG, 256>>>(W, bias, out, N);
}